// round 2
// baseline (speedup 1.0000x reference)
#include <cuda_runtime.h>

#define BATCHN 8192
#define SEQ 100
#define EMBED 50
#define HID 20
#define NLABEL 15
#define G3 60
#define VOCAB 50000
#define WARPS 4
#define RPW 8          // batch elements per warp in recurrence kernels

typedef unsigned long long ull;

// ---------------- scratch (device globals; no runtime allocation) -------------
__device__ ull d_PW1p[(size_t)VOCAB * 32];              // 12.8 MB: emb@W1+bi, pair-packed
__device__ ull d_MX2p[(size_t)BATCHN * SEQ * 32];       // 210 MB: h1@W2+bi2, pair-packed

// ---------------- packed f32x2 helpers ---------------------------------------
__device__ __forceinline__ ull pack2(float x) {
    ull d; asm("mov.b64 %0, {%1, %1};" : "=l"(d) : "f"(x)); return d;
}
__device__ __forceinline__ ull packab(float a, float b) {
    ull d; asm("mov.b64 %0, {%1, %2};" : "=l"(d) : "f"(a), "f"(b)); return d;
}
__device__ __forceinline__ void unpk(ull v, float &a, float &b) {
    asm("mov.b64 {%0, %1}, %2;" : "=f"(a), "=f"(b) : "l"(v));
}
__device__ __forceinline__ ull ffma2(ull a, ull b, ull c) {
    ull d; asm("fma.rn.f32x2 %0, %1, %2, %3;" : "=l"(d) : "l"(a), "l"(b), "l"(c)); return d;
}
__device__ __forceinline__ float sigm(float x) {
    return __fdividef(1.f, 1.f + __expf(-x));
}
__device__ __forceinline__ float tanh_(float x) {
    return 2.f * __fdividef(1.f, 1.f + __expf(-2.f * x)) - 1.f;
}

// ============================================================================
// Kernel P: PW1[v] = emb[v] @ W1 + b1_input   (pair-packed, 32 ull per row)
// warp per vocab row, W1 pair-columns in registers.
// ============================================================================
__global__ void __launch_bounds__(128) proj1_kernel(
    const float* __restrict__ emb, const float* __restrict__ W1,
    const float* __restrict__ b1)
{
    __shared__ __align__(16) ull sx[4][52];
    const int w = threadIdx.x >> 5, j = threadIdx.x & 31;

    ull w1r[EMBED];
    #pragma unroll
    for (int k = 0; k < EMBED; k++) {
        float lo = W1[k * G3 + j];
        float hi = (j + 32 < G3) ? W1[k * G3 + j + 32] : 0.f;
        w1r[k] = packab(lo, hi);
    }
    const ull bias = packab(b1[j], (j + 32 < G3) ? b1[j + 32] : 0.f);

    const int nwarps = gridDim.x * (blockDim.x >> 5);
    for (int v = blockIdx.x * (blockDim.x >> 5) + w; v < VOCAB; v += nwarps) {
        if (j < 25) {
            float2 t = *(const float2*)(emb + (size_t)v * EMBED + j * 2);
            sx[w][j * 2]     = pack2(t.x);
            sx[w][j * 2 + 1] = pack2(t.y);
        }
        __syncwarp();
        ull acc = bias;
        #pragma unroll
        for (int k = 0; k < EMBED; k += 2) {
            ulonglong2 xv = *(const ulonglong2*)&sx[w][k];
            acc = ffma2(xv.x, w1r[k], acc);
            acc = ffma2(xv.y, w1r[k + 1], acc);
        }
        d_PW1p[(size_t)v * 32 + j] = acc;
        __syncwarp();
    }
}

// ============================================================================
// Kernel B: layer-1 recurrence (gather PW1) + fused h1@W2+bi2 -> MX2
// 256 blocks x 128 thr; warp handles RPW=8 batch elements; U1,W2 in registers.
// ============================================================================
__global__ void __launch_bounds__(128, 2) gru1_kernel(
    const int* __restrict__ xg, const float* __restrict__ U1f,
    const float* __restrict__ b1, const float* __restrict__ W2f,
    const float* __restrict__ b2)
{
    __shared__ __align__(16) ull sh1[WARPS][RPW][HID];   // h1, pair-dup
    __shared__ float ss[WARPS][RPW][64];
    __shared__ float smh[WARPS][RPW][24];
    __shared__ int   sxi[WARPS][RPW][SEQ];

    const int w = threadIdx.x >> 5, j = threadIdx.x & 31;
    const int b0 = (blockIdx.x * WARPS + w) * RPW;

    ull u1r[HID], w2r[HID];
    #pragma unroll
    for (int k = 0; k < HID; k++) {
        float hiok = (j + 32 < G3) ? 1.f : 0.f;
        u1r[k] = packab(U1f[k * G3 + j], hiok * U1f[k * G3 + ((j + 32 < G3) ? j + 32 : j)]);
        w2r[k] = packab(W2f[k * G3 + j], hiok * W2f[k * G3 + ((j + 32 < G3) ? j + 32 : j)]);
    }
    const ull br1 = packab(b1[G3 + j], (j + 32 < G3) ? b1[G3 + j + 32] : 0.f);
    const ull bi2 = packab(b2[j],      (j + 32 < G3) ? b2[j + 32]      : 0.f);

    // stage all indices for this warp's 8 elements
    #pragma unroll
    for (int r = 0; r < RPW; r++) {
        if (j < 25)
            *(int4*)&sxi[w][r][j * 4] = *(const int4*)(xg + (size_t)(b0 + r) * SEQ + j * 4);
    }
    // zero h state
    for (int i = j; i < RPW * HID; i += 32) ((ull*)sh1[w])[i] = 0ull;
    float hprev[RPW];
    #pragma unroll
    for (int r = 0; r < RPW; r++) hprev[r] = 0.f;
    __syncwarp();

    // prefetch t=0 input projection (gather from L2-resident PW1)
    ull ax[RPW];
    #pragma unroll
    for (int r = 0; r < RPW; r++)
        ax[r] = d_PW1p[(size_t)sxi[w][r][0] * 32 + j];

    for (int t = 0; t < SEQ; t++) {
        // --- recurrent projection: ah = h1 @ U1 + br1 ---
        ull ah[RPW];
        #pragma unroll
        for (int r = 0; r < RPW; r++) ah[r] = br1;
        #pragma unroll
        for (int k = 0; k < HID; k += 2) {
            #pragma unroll
            for (int r = 0; r < RPW; r++) {
                ulonglong2 hv = *(const ulonglong2*)&sh1[w][r][k];
                ah[r] = ffma2(hv.x, u1r[k], ah[r]);
                ah[r] = ffma2(hv.y, u1r[k + 1], ah[r]);
            }
        }
        // --- gate sums ---
        #pragma unroll
        for (int r = 0; r < RPW; r++) {
            float axl, axh, ahl, ahh;
            unpk(ax[r], axl, axh); unpk(ah[r], ahl, ahh);
            ss[w][r][j] = axl + ahl;
            int c = j + 32;
            if (c < 40) ss[w][r][c] = axh + ahh;
            else { ss[w][r][c] = axh; smh[w][r][c - 40] = ahh; }
        }
        __syncwarp();
        // --- gate update (lanes 0..19) ---
        if (j < HID) {
            #pragma unroll
            for (int r = 0; r < RPW; r++) {
                float z  = sigm(ss[w][r][j]);
                float rr = sigm(ss[w][r][j + 20]);
                float hh = tanh_(ss[w][r][j + 40] + rr * smh[w][r][j]);
                float hn = z * hprev[r] + (1.f - z) * hh;
                hprev[r] = hn;
                sh1[w][r][j] = pack2(hn);
            }
        }
        __syncwarp();
        // --- prefetch next step's input projection ---
        if (t + 1 < SEQ) {
            #pragma unroll
            for (int r = 0; r < RPW; r++)
                ax[r] = d_PW1p[(size_t)sxi[w][r][t + 1] * 32 + j];
        }
        // --- fused layer-2 input projection: mx2 = h1 @ W2 + bi2 ---
        ull m2[RPW];
        #pragma unroll
        for (int r = 0; r < RPW; r++) m2[r] = bi2;
        #pragma unroll
        for (int k = 0; k < HID; k += 2) {
            #pragma unroll
            for (int r = 0; r < RPW; r++) {
                ulonglong2 hv = *(const ulonglong2*)&sh1[w][r][k];
                m2[r] = ffma2(hv.x, w2r[k], m2[r]);
                m2[r] = ffma2(hv.y, w2r[k + 1], m2[r]);
            }
        }
        #pragma unroll
        for (int r = 0; r < RPW; r++)
            d_MX2p[((size_t)(b0 + r) * SEQ + t) * 32 + j] = m2[r];
    }
}

// ============================================================================
// Kernel D: layer-2 recurrence reading MX2 (streamed) + dense head
// ============================================================================
__global__ void __launch_bounds__(128, 2) gru2_kernel(
    const float* __restrict__ U2f, const float* __restrict__ b2,
    const float* __restrict__ Wd, const float* __restrict__ bd,
    float* __restrict__ out)
{
    __shared__ __align__(16) ull sh2[WARPS][RPW][HID];
    __shared__ float ss[WARPS][RPW][64];
    __shared__ float smh[WARPS][RPW][24];

    const int w = threadIdx.x >> 5, j = threadIdx.x & 31;
    const int b0 = (blockIdx.x * WARPS + w) * RPW;

    ull u2r[HID];
    #pragma unroll
    for (int k = 0; k < HID; k++) {
        float lo = U2f[k * G3 + j];
        float hi = (j + 32 < G3) ? U2f[k * G3 + j + 32] : 0.f;
        u2r[k] = packab(lo, hi);
    }
    const ull br2 = packab(b2[G3 + j], (j + 32 < G3) ? b2[G3 + j + 32] : 0.f);

    for (int i = j; i < RPW * HID; i += 32) ((ull*)sh2[w])[i] = 0ull;
    float hprev[RPW];
    #pragma unroll
    for (int r = 0; r < RPW; r++) hprev[r] = 0.f;
    __syncwarp();

    ull ax[RPW];
    #pragma unroll
    for (int r = 0; r < RPW; r++)
        ax[r] = d_MX2p[((size_t)(b0 + r) * SEQ) * 32 + j];

    for (int t = 0; t < SEQ; t++) {
        ull ah[RPW];
        #pragma unroll
        for (int r = 0; r < RPW; r++) ah[r] = br2;
        #pragma unroll
        for (int k = 0; k < HID; k += 2) {
            #pragma unroll
            for (int r = 0; r < RPW; r++) {
                ulonglong2 hv = *(const ulonglong2*)&sh2[w][r][k];
                ah[r] = ffma2(hv.x, u2r[k], ah[r]);
                ah[r] = ffma2(hv.y, u2r[k + 1], ah[r]);
            }
        }
        #pragma unroll
        for (int r = 0; r < RPW; r++) {
            float axl, axh, ahl, ahh;
            unpk(ax[r], axl, axh); unpk(ah[r], ahl, ahh);
            ss[w][r][j] = axl + ahl;
            int c = j + 32;
            if (c < 40) ss[w][r][c] = axh + ahh;
            else { ss[w][r][c] = axh; smh[w][r][c - 40] = ahh; }
        }
        __syncwarp();
        if (j < HID) {
            #pragma unroll
            for (int r = 0; r < RPW; r++) {
                float z  = sigm(ss[w][r][j]);
                float rr = sigm(ss[w][r][j + 20]);
                float hh = tanh_(ss[w][r][j + 40] + rr * smh[w][r][j]);
                float hn = z * hprev[r] + (1.f - z) * hh;
                hprev[r] = hn;
                sh2[w][r][j] = pack2(hn);
            }
        }
        __syncwarp();
        if (t + 1 < SEQ) {
            #pragma unroll
            for (int r = 0; r < RPW; r++)
                ax[r] = d_MX2p[((size_t)(b0 + r) * SEQ + (t + 1)) * 32 + j];
        }
    }

    // dense head: logits = h2 @ Wd + bd  (h2 lo halves live in sh2)
    if (j < NLABEL) {
        #pragma unroll
        for (int r = 0; r < RPW; r++) {
            float acc = bd[j];
            #pragma unroll
            for (int k = 0; k < HID; k++) {
                float hv, dum; unpk(sh2[w][r][k], hv, dum);
                acc += hv * Wd[k * NLABEL + j];
            }
            out[(size_t)(b0 + r) * NLABEL + j] = acc;
        }
    }
}

// ============================================================================
extern "C" void kernel_launch(void* const* d_in, const int* in_sizes, int n_in,
                              void* d_out, int out_size) {
    const int*   x   = (const int*)d_in[0];
    const float* emb = (const float*)d_in[1];
    const float* W1  = (const float*)d_in[2];
    const float* U1  = (const float*)d_in[3];
    const float* b1  = (const float*)d_in[4];
    const float* W2  = (const float*)d_in[5];
    const float* U2  = (const float*)d_in[6];
    const float* b2  = (const float*)d_in[7];
    const float* Wd  = (const float*)d_in[8];
    const float* bd  = (const float*)d_in[9];
    (void)in_sizes; (void)n_in; (void)out_size;

    proj1_kernel<<<256, 128>>>(emb, W1, b1);
    gru1_kernel<<<BATCHN / (WARPS * RPW), 128>>>(x, U1, b1, W2, b2);
    gru2_kernel<<<BATCHN / (WARPS * RPW), 128>>>(U2, b2, Wd, bd, (float*)d_out);
}

// round 4
// speedup vs baseline: 3.4165x; 3.4165x over previous
#include <cuda_runtime.h>

#define BATCHN 8192
#define SEQ 100
#define EMBED 50
#define HID 20
#define NLABEL 15
#define G3 60
#define VOCAB 50000
#define WARPS 4
#define RPW 4

typedef unsigned long long ull;

// scratch: PW1[v] = emb[v] @ W1 + b1_input, pair-packed (col j, col j+32), 12.8 MB
__device__ ull d_PW1p[(size_t)VOCAB * 32];

__device__ __forceinline__ ull pack2(float x) {
    ull d; asm("mov.b64 %0, {%1, %1};" : "=l"(d) : "f"(x)); return d;
}
__device__ __forceinline__ ull packab(float a, float b) {
    ull d; asm("mov.b64 %0, {%1, %2};" : "=l"(d) : "f"(a), "f"(b)); return d;
}
__device__ __forceinline__ void unpk(ull v, float &a, float &b) {
    asm("mov.b64 {%0, %1}, %2;" : "=f"(a), "=f"(b) : "l"(v));
}
__device__ __forceinline__ ull ffma2(ull a, ull b, ull c) {
    ull d; asm("fma.rn.f32x2 %0, %1, %2, %3;" : "=l"(d) : "l"(a), "l"(b), "l"(c)); return d;
}
__device__ __forceinline__ float sigm(float x) {
    return __fdividef(1.f, 1.f + __expf(-x));
}
__device__ __forceinline__ float tanh_(float x) {
    return 2.f * __fdividef(1.f, 1.f + __expf(-2.f * x)) - 1.f;
}

// ============================================================================
// proj: PW1[v] = emb[v]@W1 + bi1. Block-tiled: 32 contiguous rows per tile,
// coalesced loads -> packed shared -> register W1.
// ============================================================================
__global__ void __launch_bounds__(128) proj1_kernel(
    const float* __restrict__ emb, const float* __restrict__ W1,
    const float* __restrict__ b1)
{
    __shared__ __align__(16) ull sx[32 * EMBED];   // 12.8 KB, duplicated-packed
    const int tid = threadIdx.x;
    const int w = tid >> 5, j = tid & 31;

    ull w1r[EMBED];
    #pragma unroll
    for (int k = 0; k < EMBED; k++) {
        float lo = W1[k * G3 + j];
        float hi = (j + 32 < G3) ? W1[k * G3 + j + 32] : 0.f;
        w1r[k] = packab(lo, hi);
    }
    const ull bias = packab(b1[j], (j + 32 < G3) ? b1[j + 32] : 0.f);

    const int ntiles = (VOCAB + 31) / 32;
    for (int tile = blockIdx.x; tile < ntiles; tile += gridDim.x) {
        const int row0 = tile * 32;
        const int nrow = (VOCAB - row0 < 32) ? (VOCAB - row0) : 32;
        for (int i = tid; i < nrow * EMBED; i += 128)
            sx[i] = pack2(emb[(size_t)row0 * EMBED + i]);
        __syncthreads();
        #pragma unroll
        for (int rr = 0; rr < 8; rr++) {
            int lr = w * 8 + rr;
            if (row0 + lr < VOCAB) {
                ull acc = bias;
                #pragma unroll
                for (int k = 0; k < EMBED; k += 2) {
                    ulonglong2 xv = *(const ulonglong2*)&sx[lr * EMBED + k];
                    acc = ffma2(xv.x, w1r[k], acc);
                    acc = ffma2(xv.y, w1r[k + 1], acc);
                }
                d_PW1p[(size_t)(row0 + lr) * 32 + j] = acc;
            }
        }
        __syncthreads();
    }
}

// ============================================================================
// Fused 2-layer GRU recurrence + dense head. R1 structure, phase-A replaced
// by a PW1 gather. Weights broadcast from shared; low reg count.
// ============================================================================
__global__ void __launch_bounds__(128) wordrnn_kernel(
    const int* __restrict__ xg,
    const float* __restrict__ U1f, const float* __restrict__ b1,
    const float* __restrict__ W2f, const float* __restrict__ b2,
    const float* __restrict__ U2f,
    const float* __restrict__ Wd, const float* __restrict__ bd,
    float* __restrict__ out)
{
    __shared__ __align__(16) ull sU1p[HID][32];
    __shared__ __align__(16) ull sW2p[HID][32];
    __shared__ __align__(16) ull sU2p[HID][32];
    __shared__ __align__(16) ull sh1[WARPS][RPW][HID];
    __shared__ __align__(16) ull sh2[WARPS][RPW][HID];
    __shared__ float ss [WARPS][RPW][64];
    __shared__ float smh[WARPS][RPW][24];
    __shared__ int   sxi[WARPS][RPW][SEQ];

    const int tid = threadIdx.x;
    const int w = tid >> 5, j = tid & 31;
    const int b0 = (blockIdx.x * WARPS + w) * RPW;

    // stage recurrence weights (pair-packed) into shared
    for (int i = tid; i < HID * 32; i += 128) {
        int k = i >> 5, c = i & 31;
        float hi_ok = (c + 32 < G3);
        int ch = (c + 32 < G3) ? c + 32 : c;
        sU1p[k][c] = packab(U1f[k * G3 + c], hi_ok ? U1f[k * G3 + ch] : 0.f);
        sW2p[k][c] = packab(W2f[k * G3 + c], hi_ok ? W2f[k * G3 + ch] : 0.f);
        sU2p[k][c] = packab(U2f[k * G3 + c], hi_ok ? U2f[k * G3 + ch] : 0.f);
    }
    const ull br1 = packab(b1[G3 + j], (j + 32 < G3) ? b1[G3 + j + 32] : 0.f);
    const ull bi2 = packab(b2[j],      (j + 32 < G3) ? b2[j + 32]      : 0.f);
    const ull br2 = packab(b2[G3 + j], (j + 32 < G3) ? b2[G3 + j + 32] : 0.f);

    // stage indices, zero h-state
    #pragma unroll
    for (int r = 0; r < RPW; r++) {
        if (j < 25)
            *(int4*)&sxi[w][r][j * 4] = *(const int4*)(xg + (size_t)(b0 + r) * SEQ + j * 4);
    }
    for (int i = j; i < RPW * HID; i += 32) {
        ((ull*)sh1[w])[i] = 0ull;
        ((ull*)sh2[w])[i] = 0ull;
    }
    float hp1[RPW], hp2[RPW];
    #pragma unroll
    for (int r = 0; r < RPW; r++) { hp1[r] = 0.f; hp2[r] = 0.f; }
    __syncthreads();

    // t=0 input projection gather (L2-resident PW1)
    ull ax[RPW];
    #pragma unroll
    for (int r = 0; r < RPW; r++)
        ax[r] = __ldg(&d_PW1p[(size_t)sxi[w][r][0] * 32 + j]);

    for (int t = 0; t < SEQ; t++) {
        // ---- layer-1 recurrent projection: ah = h1 @ U1 + br1 ----
        ull ah[RPW];
        #pragma unroll
        for (int r = 0; r < RPW; r++) ah[r] = br1;
        #pragma unroll
        for (int k = 0; k < HID; k += 2) {
            ulonglong2 uv = *(const ulonglong2*)&sU1p[k][0] ; // dummy to keep layout
            (void)uv;
            ull u0 = sU1p[k][j], u1 = sU1p[k + 1][j];
            #pragma unroll
            for (int r = 0; r < RPW; r++) {
                ulonglong2 hv = *(const ulonglong2*)&sh1[w][r][k];
                ah[r] = ffma2(hv.x, u0, ah[r]);
                ah[r] = ffma2(hv.y, u1, ah[r]);
            }
        }
        #pragma unroll
        for (int r = 0; r < RPW; r++) {
            float axl, axh, ahl, ahh;
            unpk(ax[r], axl, axh); unpk(ah[r], ahl, ahh);
            ss[w][r][j] = axl + ahl;
            int c = j + 32;
            if (c < 40) ss[w][r][c] = axh + ahh;
            else { ss[w][r][c] = axh; smh[w][r][c - 40] = ahh; }
        }
        __syncwarp();
        if (j < HID) {
            #pragma unroll
            for (int r = 0; r < RPW; r++) {
                float z  = sigm(ss[w][r][j]);
                float rr = sigm(ss[w][r][j + 20]);
                float hh = tanh_(ss[w][r][j + 40] + rr * smh[w][r][j]);
                float hn = z * hp1[r] + (1.f - z) * hh;
                hp1[r] = hn;
                sh1[w][r][j] = pack2(hn);
            }
        }
        __syncwarp();

        // prefetch next step's input projection (latency hidden behind layer 2)
        if (t + 1 < SEQ) {
            #pragma unroll
            for (int r = 0; r < RPW; r++)
                ax[r] = __ldg(&d_PW1p[(size_t)sxi[w][r][t + 1] * 32 + j]);
        }

        // ---- layer-2: mx2 = h1@W2 + bi2 ; ah2 = h2@U2 + br2 ----
        ull m2[RPW], a2[RPW];
        #pragma unroll
        for (int r = 0; r < RPW; r++) { m2[r] = bi2; a2[r] = br2; }
        #pragma unroll
        for (int k = 0; k < HID; k += 2) {
            ull w0 = sW2p[k][j], w1 = sW2p[k + 1][j];
            ull u0 = sU2p[k][j], u1 = sU2p[k + 1][j];
            #pragma unroll
            for (int r = 0; r < RPW; r++) {
                ulonglong2 h1v = *(const ulonglong2*)&sh1[w][r][k];
                ulonglong2 h2v = *(const ulonglong2*)&sh2[w][r][k];
                m2[r] = ffma2(h1v.x, w0, m2[r]);
                m2[r] = ffma2(h1v.y, w1, m2[r]);
                a2[r] = ffma2(h2v.x, u0, a2[r]);
                a2[r] = ffma2(h2v.y, u1, a2[r]);
            }
        }
        #pragma unroll
        for (int r = 0; r < RPW; r++) {
            float axl, axh, ahl, ahh;
            unpk(m2[r], axl, axh); unpk(a2[r], ahl, ahh);
            ss[w][r][j] = axl + ahl;
            int c = j + 32;
            if (c < 40) ss[w][r][c] = axh + ahh;
            else { ss[w][r][c] = axh; smh[w][r][c - 40] = ahh; }
        }
        __syncwarp();
        if (j < HID) {
            #pragma unroll
            for (int r = 0; r < RPW; r++) {
                float z  = sigm(ss[w][r][j]);
                float rr = sigm(ss[w][r][j + 20]);
                float hh = tanh_(ss[w][r][j + 40] + rr * smh[w][r][j]);
                float hn = z * hp2[r] + (1.f - z) * hh;
                hp2[r] = hn;
                sh2[w][r][j] = pack2(hn);
            }
        }
        __syncwarp();
    }

    // ---- dense head ----
    if (j < NLABEL) {
        #pragma unroll
        for (int r = 0; r < RPW; r++) {
            float acc = bd[j];
            #pragma unroll
            for (int k = 0; k < HID; k++) {
                float hv, dum; unpk(sh2[w][r][k], hv, dum);
                acc += hv * Wd[k * NLABEL + j];
            }
            out[(size_t)(b0 + r) * NLABEL + j] = acc;
        }
    }
}

extern "C" void kernel_launch(void* const* d_in, const int* in_sizes, int n_in,
                              void* d_out, int out_size) {
    const int*   x   = (const int*)d_in[0];
    const float* emb = (const float*)d_in[1];
    const float* W1  = (const float*)d_in[2];
    const float* U1  = (const float*)d_in[3];
    const float* b1  = (const float*)d_in[4];
    const float* W2  = (const float*)d_in[5];
    const float* U2  = (const float*)d_in[6];
    const float* b2  = (const float*)d_in[7];
    const float* Wd  = (const float*)d_in[8];
    const float* bd  = (const float*)d_in[9];
    (void)in_sizes; (void)n_in; (void)out_size;

    proj1_kernel<<<512, 128>>>(emb, W1, b1);
    wordrnn_kernel<<<BATCHN / (WARPS * RPW), 128>>>(
        x, U1, b1, W2, b2, U2, Wd, bd, (float*)d_out);
}